// round 17
// baseline (speedup 1.0000x reference)
#include <cuda_runtime.h>
#include <cuda_bf16.h>
#include <cstdint>

#define NN 50000
#define EE 600000
#define CC 128

// Scratch (device globals — no runtime allocation allowed)
__device__ float        g_xw[NN * CC];
__device__ float        g_agg[NN * CC];
__device__ float        g_dinv[NN];
__device__ unsigned int g_deg[NN];

// ---------------------------------------------------------------------------
// K0: zero degree counters
// ---------------------------------------------------------------------------
__global__ void k_zero_deg(int n) {
    int i = blockIdx.x * blockDim.x + threadIdx.x;
    if (i < n) g_deg[i] = 0u;
}

// ---------------------------------------------------------------------------
// K1: degree histogram over dst
// ---------------------------------------------------------------------------
__global__ void k_count(const int* __restrict__ ei, int E) {
    int e = blockIdx.x * blockDim.x + threadIdx.x;
    if (e < E) atomicAdd(&g_deg[ei[E + e]], 1u);
}

// ---------------------------------------------------------------------------
// K1b: dinv = rsqrt(deg + 1)
// ---------------------------------------------------------------------------
__global__ void k_dinv(int n) {
    int i = blockIdx.x * blockDim.x + threadIdx.x;
    if (i < n) g_dinv[i] = rsqrtf((float)g_deg[i] + 1.0f);
}

// ---------------------------------------------------------------------------
// K2: xw = x @ W via tf32 mma.sync.m16n8k8, cp.async 2-stage pipeline.
//     Block tile 64x128 (was 128x128): 8 warps as 2(m) x 4(n), acc=32 regs
//     -> ~80 regs/thread -> 3 CTA/SM -> kills the 1.32-wave tail.
//     K chunked by 16 (8 chunks); smem = 2*64*20*4 + 2*16*136*4 = 27,648 B.
//     Raw f32 bits feed the tf32 MMA (HW truncation).
//     Epilogue writes g_xw and g_agg = xw * dinv^2 (self-loop init).
//
//     Conflict-free fragment banks:
//       xs k-stride 20:  bank = (20g + c) mod 32 -> all 32 distinct
//       ws n-stride 136: bank = (8c + g) mod 32  -> all 32 distinct
// ---------------------------------------------------------------------------
#define XS_WORDS (64 * 20)
#define WS_WORDS (16 * 136)

__device__ __forceinline__ void cp16(uint32_t smem_addr, const void* gptr) {
    asm volatile("cp.async.cg.shared.global [%0], [%1], 16;"
                 :: "r"(smem_addr), "l"(gptr));
}

__global__ __launch_bounds__(256) void k_gemm_tc(const float* __restrict__ x,
                                                 const float* __restrict__ W,
                                                 int n) {
    __shared__ uint32_t xs[2][XS_WORDS];   // [stage][m][k], k-stride 20
    __shared__ uint32_t ws[2][WS_WORDS];   // [stage][k][n], n-stride 136

    const int t      = threadIdx.x;
    const int lane   = t & 31;
    const int warp   = t >> 5;
    const int g      = lane >> 2;
    const int c      = lane & 3;
    const int warp_m = warp >> 2;       // 0..1  (32 rows each)
    const int warp_n = warp & 3;        // 0..3  (32 cols each)
    const int row0   = blockIdx.x * 64;

    uint32_t xs_base[2], ws_base[2];
    {
        uint32_t a0, a1;
        asm("{ .reg .u64 tt; cvta.to.shared.u64 tt, %2; cvt.u32.u64 %0, tt;\n\t"
            "  .reg .u64 uu; cvta.to.shared.u64 uu, %3; cvt.u32.u64 %1, uu; }"
            : "=r"(a0), "=r"(a1) : "l"(&xs[0][0]), "l"(&ws[0][0]));
        xs_base[0] = a0; xs_base[1] = a0 + XS_WORDS * 4;
        ws_base[0] = a1; ws_base[1] = a1 + WS_WORDS * 4;
    }

    // issue all cp.asyncs for K-chunk kc (16 wide) into stage s
    auto load_stage = [&](int kc, int s) {
        // x tile: 64 rows x 16 k -> 256 16B copies (1 per thread)
        {
            int j  = t;                 // 0..255
            int r  = j >> 2;            // 0..63
            int k4 = j & 3;             // 0..3
            int row = row0 + r;
            if (row >= n) row = n - 1;
            cp16(xs_base[s] + (r * 20 + k4 * 4) * 4,
                 &((const float4*)x)[row * 32 + (kc >> 2) + k4]);
        }
        // W chunk: 16 k x 128 n -> 512 16B copies (2 per thread)
#pragma unroll
        for (int j = t; j < 512; j += 256) {
            int k  = j >> 5;            // 0..15
            int n4 = j & 31;            // 0..31
            cp16(ws_base[s] + (k * 136 + n4 * 4) * 4,
                 &((const float4*)W)[(kc + k) * 32 + n4]);
        }
        asm volatile("cp.async.commit_group;" ::: "memory");
    };

    float acc[2][4][4];
#pragma unroll
    for (int mt = 0; mt < 2; mt++)
#pragma unroll
        for (int nt = 0; nt < 4; nt++)
#pragma unroll
            for (int q = 0; q < 4; q++) acc[mt][nt][q] = 0.0f;

    load_stage(0, 0);

#pragma unroll
    for (int kci = 0; kci < 8; kci++) {
        const int s = kci & 1;
        if (kci < 7) {
            load_stage((kci + 1) * 16, s ^ 1);
            asm volatile("cp.async.wait_group 1;" ::: "memory");
        } else {
            asm volatile("cp.async.wait_group 0;" ::: "memory");
        }
        __syncthreads();

        const uint32_t* xsp = &xs[s][0];
        const uint32_t* wsp = &ws[s][0];
#pragma unroll
        for (int ks = 0; ks < 16; ks += 8) {
            uint32_t a[2][4];
#pragma unroll
            for (int mt = 0; mt < 2; mt++) {
                int mrow = warp_m * 32 + mt * 16 + g;
                a[mt][0] = xsp[mrow * 20 + ks + c];
                a[mt][1] = xsp[(mrow + 8) * 20 + ks + c];
                a[mt][2] = xsp[mrow * 20 + ks + c + 4];
                a[mt][3] = xsp[(mrow + 8) * 20 + ks + c + 4];
            }
            uint32_t b[4][2];
#pragma unroll
            for (int nt = 0; nt < 4; nt++) {
                int ncol = warp_n * 32 + nt * 8 + g;
                b[nt][0] = wsp[(ks + c) * 136 + ncol];
                b[nt][1] = wsp[(ks + c + 4) * 136 + ncol];
            }
#pragma unroll
            for (int mt = 0; mt < 2; mt++)
#pragma unroll
                for (int nt = 0; nt < 4; nt++) {
                    asm volatile(
                        "mma.sync.aligned.m16n8k8.row.col.f32.tf32.tf32.f32 "
                        "{%0,%1,%2,%3}, {%4,%5,%6,%7}, {%8,%9}, {%0,%1,%2,%3};"
                        : "+f"(acc[mt][nt][0]), "+f"(acc[mt][nt][1]),
                          "+f"(acc[mt][nt][2]), "+f"(acc[mt][nt][3])
                        : "r"(a[mt][0]), "r"(a[mt][1]), "r"(a[mt][2]), "r"(a[mt][3]),
                          "r"(b[nt][0]), "r"(b[nt][1]));
                }
        }
        __syncthreads();
    }

    // epilogue: c0/c1 -> (row g,   cols 2c, 2c+1); c2/c3 -> (row g+8, ...)
#pragma unroll
    for (int mt = 0; mt < 2; mt++) {
#pragma unroll
        for (int half = 0; half < 2; half++) {
            int row = row0 + warp_m * 32 + mt * 16 + g + half * 8;
            if (row < n) {
                float dv = g_dinv[row];
                float s2 = dv * dv;
#pragma unroll
                for (int nt = 0; nt < 4; nt++) {
                    int col = warp_n * 32 + nt * 8 + c * 2;
                    float v0 = acc[mt][nt][half * 2];
                    float v1 = acc[mt][nt][half * 2 + 1];
                    ((float2*)g_xw)[(row * 128 + col) >> 1]  = make_float2(v0, v1);
                    ((float2*)g_agg)[(row * 128 + col) >> 1] = make_float2(v0 * s2, v1 * s2);
                }
            }
        }
    }
}

// ---------------------------------------------------------------------------
// K3: edge scatter — one warp per edge, vector RED into agg[dst]
// ---------------------------------------------------------------------------
__global__ void k_scatter(const int* __restrict__ ei, int E) {
    int gt   = blockIdx.x * blockDim.x + threadIdx.x;
    int e    = gt >> 5;
    int lane = gt & 31;
    if (e >= E) return;
    int src = __ldg(&ei[e]);
    int dst = __ldg(&ei[E + e]);
    float norm = g_dinv[src] * g_dinv[dst];
    float4 v = ((const float4*)g_xw)[src * 32 + lane];
    v.x *= norm; v.y *= norm; v.z *= norm; v.w *= norm;
    float* p = g_agg + (size_t)dst * CC + lane * 4;
    asm volatile("red.global.add.v4.f32 [%0], {%1, %2, %3, %4};"
                 :: "l"(p), "f"(v.x), "f"(v.y), "f"(v.z), "f"(v.w)
                 : "memory");
}

// ---------------------------------------------------------------------------
// K4: finalize — bias, LayerNorm(C=128), LeakyReLU, residual. One warp/node.
// ---------------------------------------------------------------------------
__global__ void k_finalize(const float* __restrict__ x,
                           const float* __restrict__ b,
                           const float* __restrict__ gamma,
                           const float* __restrict__ beta,
                           float* __restrict__ out, int n) {
    int gt   = blockIdx.x * blockDim.x + threadIdx.x;
    int node = gt >> 5;
    int lane = gt & 31;
    if (node >= n) return;

    float4 v  = ((const float4*)g_agg)[node * 32 + lane];
    float4 bv = ((const float4*)b)[lane];
    v.x += bv.x; v.y += bv.y; v.z += bv.z; v.w += bv.w;

    float sum = v.x + v.y + v.z + v.w;
#pragma unroll
    for (int off = 16; off > 0; off >>= 1)
        sum += __shfl_xor_sync(0xffffffffu, sum, off);
    float mean = sum * (1.0f / 128.0f);

    float cx = v.x - mean, cy = v.y - mean, cz = v.z - mean, cw = v.w - mean;
    float sq = cx * cx + cy * cy + cz * cz + cw * cw;
#pragma unroll
    for (int off = 16; off > 0; off >>= 1)
        sq += __shfl_xor_sync(0xffffffffu, sq, off);
    float var  = sq * (1.0f / 128.0f);
    float rstd = rsqrtf(var + 1e-5f);

    float4 g  = ((const float4*)gamma)[lane];
    float4 be = ((const float4*)beta)[lane];
    float4 xr = ((const float4*)x)[node * 32 + lane];

    float4 o;
    o.x = fmaf(cx * rstd, g.x, be.x);
    o.y = fmaf(cy * rstd, g.y, be.y);
    o.z = fmaf(cz * rstd, g.z, be.z);
    o.w = fmaf(cw * rstd, g.w, be.w);
    o.x = (o.x >= 0.0f ? o.x : 0.01f * o.x) + xr.x;
    o.y = (o.y >= 0.0f ? o.y : 0.01f * o.y) + xr.y;
    o.z = (o.z >= 0.0f ? o.z : 0.01f * o.z) + xr.z;
    o.w = (o.w >= 0.0f ? o.w : 0.01f * o.w) + xr.w;

    ((float4*)out)[node * 32 + lane] = o;
}

// ---------------------------------------------------------------------------
// Host launcher (graph-capturable: kernel launches only, default stream)
// ---------------------------------------------------------------------------
extern "C" void kernel_launch(void* const* d_in, const int* in_sizes, int n_in,
                              void* d_out, int out_size) {
    const float* x     = (const float*)d_in[0];
    const int*   ei    = (const int*)d_in[1];
    const float* W     = (const float*)d_in[2];
    const float* b     = (const float*)d_in[3];
    const float* gamma = (const float*)d_in[4];
    const float* beta  = (const float*)d_in[5];
    float* out = (float*)d_out;

    const int n = in_sizes[0] / CC;      // 50000
    const int E = in_sizes[1] / 2;       // 600000

    k_zero_deg<<<(n + 255) / 256, 256>>>(n);
    k_count<<<(E + 255) / 256, 256>>>(ei, E);
    k_dinv<<<(n + 255) / 256, 256>>>(n);
    k_gemm_tc<<<(n + 63) / 64, 256>>>(x, W, n);
    k_scatter<<<((long long)E * 32 + 255) / 256, 256>>>(ei, E);
    k_finalize<<<(n * 32 + 255) / 256, 256>>>(x, b, gamma, beta, out, n);
}